// round 4
// baseline (speedup 1.0000x reference)
#include <cuda_runtime.h>
#include <cuda_bf16.h>
#include <math.h>
#include <stdint.h>

// ---------------- problem constants ----------------
#define BATCH   4
#define SEQ     2048
#define HID     1024
#define DS      256          // per-scale dim
#define NH      2            // heads per scale
#define HD      128          // head dim
#define MROWS   (BATCH*SEQ)  // 8192

// ---------------- scratch (device globals; no allocation allowed) ----------------
__device__ float g_Q [MROWS*HID];
__device__ float g_K [MROWS*HID];
__device__ float g_V [MROWS*HID];
__device__ float g_QH[4L*MROWS*DS];
__device__ float g_KH[4L*MROWS*DS];
__device__ float g_VH[4L*MROWS*DS];
__device__ float g_VT[MROWS*DS];                      // transposed V heads (per scale, reused)
__device__ float g_KP[4L*BATCH*(SEQ/2)*DS];
__device__ float g_VP[4L*BATCH*(SEQ/2)*DS];
__device__ float g_S [(long long)BATCH*NH*SEQ*SEQ];   // scores (reused per scale)
__device__ float g_OH[MROWS*DS];                      // reused per scale
__device__ float g_ATT[MROWS*HID];

// ---------------- helpers ----------------
__device__ __forceinline__ uint32_t smem_u32(const void* p) {
    uint32_t a;
    asm("{ .reg .u64 t; cvta.to.shared.u64 t, %1; cvt.u32.u64 %0, t; }" : "=r"(a) : "l"(p));
    return a;
}

__device__ __forceinline__ void ldm4(uint32_t* r, uint32_t addr) {
    asm volatile("ldmatrix.sync.aligned.m8n8.x4.shared.b16 {%0,%1,%2,%3}, [%4];"
                 : "=r"(r[0]), "=r"(r[1]), "=r"(r[2]), "=r"(r[3]) : "r"(addr));
}

__device__ __forceinline__ void mma_bf16(float* c, const uint32_t* a, uint32_t b0, uint32_t b1) {
    asm volatile("mma.sync.aligned.m16n8k16.row.col.f32.bf16.bf16.f32 "
                 "{%0,%1,%2,%3},{%4,%5,%6,%7},{%8,%9},{%0,%1,%2,%3};"
                 : "+f"(c[0]), "+f"(c[1]), "+f"(c[2]), "+f"(c[3])
                 : "r"(a[0]), "r"(a[1]), "r"(a[2]), "r"(a[3]), "r"(b0), "r"(b1));
}

// ---------------- bf16x2 split tensor-core GEMM ----------------
// C = alpha * A @ B^T + bias.  A: M x K row-major (lda), B: N x K row-major (ldb).
// M, N multiples of 128; K multiple of 32 (true for every call site).
// 512 threads, 128x128 CTA tile, 32x32 warp tile, double-buffered smem.
#define BM 128
#define BN 128
#define BKS 32
#define LDT 40                           // smem row stride in bf16 elems
#define MAT_ELEMS (BM * LDT)             // 5120 bf16 per matrix
#define STAGE_ELEMS (4 * MAT_ELEMS)      // Ah, Al, Bh, Bl
#define GEMM_SMEM (2 * STAGE_ELEMS * 2)  // bytes = 81920

__global__ void __launch_bounds__(512)
gemm_bf16x2(const float* __restrict__ A, const float* __restrict__ Bm,
            const float* __restrict__ bias, float* __restrict__ C,
            int M, int N, int K, int lda, int ldb, int ldc,
            long long sAb, long long sAh, long long sBb, long long sBh,
            long long sCb, long long sCh, int nh, float alpha)
{
    int z = blockIdx.z;
    int bb = z / nh, hh = z - bb * nh;
    A  += (long long)bb * sAb + (long long)hh * sAh;
    Bm += (long long)bb * sBb + (long long)hh * sBh;
    C  += (long long)bb * sCb + (long long)hh * sCh;

    extern __shared__ __nv_bfloat16 smbuf[];

    const int tid   = threadIdx.x;
    const int lane  = tid & 31;
    const int wid   = tid >> 5;
    const int warpM = wid & 3;           // 4 warps in m (32 rows each)
    const int warpN = wid >> 2;          // 4 warps in n (32 cols each)
    const int row0  = blockIdx.y * BM;
    const int col0  = blockIdx.x * BN;

    // global tile load: 8 threads per row (float4 each), 64 rows per wave, 2 waves
    const int gr = tid >> 3;             // 0..63
    const int gc = (tid & 7) << 2;       // 0,4,...,28

    float4 aReg[2], bReg[2];

    // smem bases per [stage][matrix]
    uint32_t sb[2][4];
#pragma unroll
    for (int st = 0; st < 2; st++)
#pragma unroll
        for (int m = 0; m < 4; m++)
            sb[st][m] = smem_u32(smbuf + (st * 4 + m) * MAT_ELEMS);

    const int aRow = warpM * 32 + (lane & 7) + ((lane >> 3) & 1) * 8;
    const int aCol = (lane >> 4) * 8;
    const int bRow = warpN * 32 + (lane & 7) + (lane >> 4) * 8;
    const int bCol = ((lane >> 3) & 1) * 8;

    uint32_t aOff[2], bOff[2];
#pragma unroll
    for (int mi = 0; mi < 2; mi++) aOff[mi] = (uint32_t)(((aRow + mi * 16) * LDT + aCol) * 2);
#pragma unroll
    for (int p = 0; p < 2; p++)    bOff[p] = (uint32_t)(((bRow + p * 16) * LDT + bCol) * 2);

    float acc[2][4][4];
#pragma unroll
    for (int mi = 0; mi < 2; mi++)
#pragma unroll
        for (int na = 0; na < 4; na++)
#pragma unroll
            for (int q = 0; q < 4; q++) acc[mi][na][q] = 0.f;

    auto ldTiles = [&](int k0) {
#pragma unroll
        for (int it = 0; it < 2; ++it) {
            aReg[it] = *(const float4*)(A  + (long long)(row0 + gr + it * 64) * lda + k0 + gc);
            bReg[it] = *(const float4*)(Bm + (long long)(col0 + gr + it * 64) * ldb + k0 + gc);
        }
    };
    auto stTiles = [&](int st) {
        __nv_bfloat16* Ah = smbuf + (st * 4 + 0) * MAT_ELEMS;
        __nv_bfloat16* Al = smbuf + (st * 4 + 1) * MAT_ELEMS;
        __nv_bfloat16* Bh = smbuf + (st * 4 + 2) * MAT_ELEMS;
        __nv_bfloat16* Bl = smbuf + (st * 4 + 3) * MAT_ELEMS;
#pragma unroll
        for (int it = 0; it < 2; ++it) {
            float va[4] = {aReg[it].x, aReg[it].y, aReg[it].z, aReg[it].w};
            float vb[4] = {bReg[it].x, bReg[it].y, bReg[it].z, bReg[it].w};
            union Pk { __nv_bfloat16 b[4]; uint2 u; } ah, al, bh, bl;
#pragma unroll
            for (int j = 0; j < 4; j++) {
                __nv_bfloat16 h = __float2bfloat16(va[j]);
                ah.b[j] = h;
                al.b[j] = __float2bfloat16(va[j] - __bfloat162float(h));
                __nv_bfloat16 h2 = __float2bfloat16(vb[j]);
                bh.b[j] = h2;
                bl.b[j] = __float2bfloat16(vb[j] - __bfloat162float(h2));
            }
            int off = (gr + it * 64) * LDT + gc;
            *(uint2*)&Ah[off] = ah.u;
            *(uint2*)&Al[off] = al.u;
            *(uint2*)&Bh[off] = bh.u;
            *(uint2*)&Bl[off] = bl.u;
        }
    };

    ldTiles(0);
    stTiles(0);
    __syncthreads();

    int st = 0;
    for (int k0 = 0; k0 < K; k0 += BKS) {
        const bool more = (k0 + BKS) < K;
        if (more) ldTiles(k0 + BKS);

#pragma unroll
        for (int ka = 0; ka < BKS; ka += 16) {
            uint32_t ah[2][4], al[2][4], bh[2][4], bl[2][4];
#pragma unroll
            for (int mi = 0; mi < 2; mi++) {
                ldm4(ah[mi], sb[st][0] + aOff[mi] + ka * 2);
                ldm4(al[mi], sb[st][1] + aOff[mi] + ka * 2);
            }
#pragma unroll
            for (int p = 0; p < 2; p++) {
                ldm4(bh[p], sb[st][2] + bOff[p] + ka * 2);
                ldm4(bl[p], sb[st][3] + bOff[p] + ka * 2);
            }
#pragma unroll
            for (int mi = 0; mi < 2; mi++)
#pragma unroll
                for (int p = 0; p < 2; p++)
#pragma unroll
                    for (int s = 0; s < 2; s++) {
                        int na = p * 2 + s;
                        mma_bf16(acc[mi][na], ah[mi], bh[p][2 * s], bh[p][2 * s + 1]);
                        mma_bf16(acc[mi][na], ah[mi], bl[p][2 * s], bl[p][2 * s + 1]);
                        mma_bf16(acc[mi][na], al[mi], bh[p][2 * s], bh[p][2 * s + 1]);
                    }
        }

        if (more) stTiles(st ^ 1);
        __syncthreads();
        st ^= 1;
    }

    // epilogue
    const int crow  = row0 + warpM * 32 + (lane >> 2);
    const int ccol0 = col0 + warpN * 32 + (lane & 3) * 2;
#pragma unroll
    for (int mi = 0; mi < 2; mi++) {
#pragma unroll
        for (int na = 0; na < 4; na++) {
            int r = crow + mi * 16;
            int c = ccol0 + na * 8;
            float b0 = bias ? bias[c]     : 0.f;
            float b1 = bias ? bias[c + 1] : 0.f;
            float2 v0 = make_float2(acc[mi][na][0] * alpha + b0, acc[mi][na][1] * alpha + b1);
            float2 v1 = make_float2(acc[mi][na][2] * alpha + b0, acc[mi][na][3] * alpha + b1);
            *(float2*)&C[(long long)r * ldc + c]       = v0;
            *(float2*)&C[(long long)(r + 8) * ldc + c] = v1;
        }
    }
}

// ---------------- avg-pool of a DS-wide column slice along seq ----------------
__global__ void pool_kernel(const float* __restrict__ X, float* __restrict__ Y,
                            int rows, int s, int colOff)
{
    int idx = blockIdx.x * blockDim.x + threadIdx.x;
    int total = rows * DS;
    if (idx >= total) return;
    int r = idx / DS, c = idx - r * DS;
    const float* src = X + (long long)r * s * HID + colOff + c;
    float acc = 0.f;
    for (int j = 0; j < s; j++) acc += src[(long long)j * HID];
    Y[idx] = acc * (1.f / s);
}

// ---------------- transpose V heads: X [B][Lk][DS] -> Y [B][NH][HD][Lk] ----------------
__global__ void transpose_vh(const float* __restrict__ X, float* __restrict__ Y, int Lk)
{
    __shared__ float t[32][33];
    int b  = blockIdx.z;
    int k0 = blockIdx.x * 32, d0 = blockIdx.y * 32;
    int tx = threadIdx.x, ty = threadIdx.y;   // 32 x 8
#pragma unroll
    for (int j = 0; j < 32; j += 8)
        t[ty + j][tx] = X[((long long)b * Lk + k0 + ty + j) * DS + d0 + tx];
    __syncthreads();
    int head = d0 >> 7;
    int dh0  = d0 & 127;
#pragma unroll
    for (int j = 0; j < 32; j += 8) {
        int d = dh0 + ty + j;
        Y[(long long)b * DS * Lk + (long long)head * HD * Lk + (long long)d * Lk + k0 + tx]
            = t[tx][ty + j];
    }
}

// ---------------- in-place row softmax ----------------
__global__ void softmax_kernel(float* __restrict__ S, int Lk)
{
    long long row = (long long)blockIdx.y * gridDim.x + blockIdx.x;
    float* p = S + row * Lk;
    __shared__ float red[256];
    int tid = threadIdx.x;

    float m = -1e30f;
    for (int i = tid; i < Lk; i += 256) m = fmaxf(m, p[i]);
    red[tid] = m; __syncthreads();
    for (int s = 128; s > 0; s >>= 1) {
        if (tid < s) red[tid] = fmaxf(red[tid], red[tid + s]);
        __syncthreads();
    }
    m = red[0]; __syncthreads();

    float sum = 0.f;
    for (int i = tid; i < Lk; i += 256) {
        float e = __expf(p[i] - m);
        p[i] = e; sum += e;
    }
    red[tid] = sum; __syncthreads();
    for (int s = 128; s > 0; s >>= 1) {
        if (tid < s) red[tid] += red[tid + s];
        __syncthreads();
    }
    float inv = 1.f / red[0];
    for (int i = tid; i < Lk; i += 256) p[i] *= inv;
}

// ---------------- mean of 2 heads of scale-0 probs -> weights0 ----------------
__global__ void meanw_kernel(const float* __restrict__ S, float* __restrict__ W)
{
    long long idx = (long long)blockIdx.x * blockDim.x + threadIdx.x;
    const long long per = (long long)SEQ * SEQ;
    const long long total = (long long)BATCH * per;
    if (idx >= total) return;
    long long b = idx / per, rest = idx - b * per;
    W[idx] = 0.5f * (S[(b * 2 + 0) * per + rest] + S[(b * 2 + 1) * per + rest]);
}

// ---------------- host orchestration ----------------
extern "C" void kernel_launch(void* const* d_in, const int* in_sizes, int n_in,
                              void* d_out, int out_size)
{
    const float* query = (const float*)d_in[0];
    const float* key_  = (const float*)d_in[1];
    const float* value = (const float*)d_in[2];
    const float* wq    = (const float*)d_in[3];
    const float* bq    = (const float*)d_in[4];
    const float* wk    = (const float*)d_in[5];
    const float* bk    = (const float*)d_in[6];
    const float* wv    = (const float*)d_in[7];
    const float* bv    = (const float*)d_in[8];
    const float* in_w  = (const float*)d_in[9];   // (4, 768, 256)
    const float* in_b  = (const float*)d_in[10];  // (4, 768)
    const float* out_w = (const float*)d_in[11];  // (4, 256, 256)
    const float* out_b = (const float*)d_in[12];  // (4, 256)
    const float* fus_w = (const float*)d_in[13];
    const float* fus_b = (const float*)d_in[14];
    float* out = (float*)d_out;

    float *Q, *K, *V, *QH, *KH, *VH, *VT, *KP, *VP, *Sb, *OH, *ATT;
    cudaGetSymbolAddress((void**)&Q,  g_Q);
    cudaGetSymbolAddress((void**)&K,  g_K);
    cudaGetSymbolAddress((void**)&V,  g_V);
    cudaGetSymbolAddress((void**)&QH, g_QH);
    cudaGetSymbolAddress((void**)&KH, g_KH);
    cudaGetSymbolAddress((void**)&VH, g_VH);
    cudaGetSymbolAddress((void**)&VT, g_VT);
    cudaGetSymbolAddress((void**)&KP, g_KP);
    cudaGetSymbolAddress((void**)&VP, g_VP);
    cudaGetSymbolAddress((void**)&Sb, g_S);
    cudaGetSymbolAddress((void**)&OH, g_OH);
    cudaGetSymbolAddress((void**)&ATT, g_ATT);

    cudaFuncSetAttribute(gemm_bf16x2, cudaFuncAttributeMaxDynamicSharedMemorySize, GEMM_SMEM);

    const dim3 blk(512);
    const float alpha_s = 0.08838834764831845f;   // 1/sqrt(128)
    const int scales[4] = {1, 2, 4, 8};

    // ---- 1. input projections: Q/K/V = X @ W^T + b
    dim3 g1(HID / BN, MROWS / BM, 1);
    gemm_bf16x2<<<g1, blk, GEMM_SMEM>>>(query, wq, bq, Q, MROWS, HID, HID, HID, HID, HID,
                                        0, 0, 0, 0, 0, 0, 1, 1.f);
    gemm_bf16x2<<<g1, blk, GEMM_SMEM>>>(key_,  wk, bk, K, MROWS, HID, HID, HID, HID, HID,
                                        0, 0, 0, 0, 0, 0, 1, 1.f);
    gemm_bf16x2<<<g1, blk, GEMM_SMEM>>>(value, wv, bv, V, MROWS, HID, HID, HID, HID, HID,
                                        0, 0, 0, 0, 0, 0, 1, 1.f);

    for (int i = 0; i < 4; i++) {
        const int s  = scales[i];
        const int Lk = SEQ / s;
        const int Mk = BATCH * Lk;
        float* QHi = QH + (long long)i * MROWS * DS;
        float* KHi = KH + (long long)i * MROWS * DS;
        float* VHi = VH + (long long)i * MROWS * DS;
        const float* wi = in_w + (long long)i * 3 * DS * DS;
        const float* bi = in_b + (long long)i * 3 * DS;

        // ---- 2. q head projection
        dim3 gq(DS / BN, MROWS / BM, 1);
        gemm_bf16x2<<<gq, blk, GEMM_SMEM>>>(Q + i * DS, wi, bi, QHi,
                                            MROWS, DS, DS, HID, DS, DS,
                                            0, 0, 0, 0, 0, 0, 1, 1.f);

        // ---- 3. pooled k/v sources
        const float* kSrc; const float* vSrc; int pl;
        if (s == 1) { kSrc = K + i * DS; vSrc = V + i * DS; pl = HID; }
        else {
            float* KPi = KP + (long long)i * BATCH * (SEQ / 2) * DS;
            float* VPi = VP + (long long)i * BATCH * (SEQ / 2) * DS;
            int total = Mk * DS;
            pool_kernel<<<(total + 255) / 256, 256>>>(K, KPi, Mk, s, i * DS);
            pool_kernel<<<(total + 255) / 256, 256>>>(V, VPi, Mk, s, i * DS);
            kSrc = KPi; vSrc = VPi; pl = DS;
        }

        // ---- 4. k/v head projections
        dim3 gk(DS / BN, Mk / BM, 1);
        gemm_bf16x2<<<gk, blk, GEMM_SMEM>>>(kSrc, wi + DS * DS, bi + DS, KHi,
                                            Mk, DS, DS, pl, DS, DS,
                                            0, 0, 0, 0, 0, 0, 1, 1.f);
        gemm_bf16x2<<<gk, blk, GEMM_SMEM>>>(vSrc, wi + 2 * DS * DS, bi + 2 * DS, VHi,
                                            Mk, DS, DS, pl, DS, DS,
                                            0, 0, 0, 0, 0, 0, 1, 1.f);

        // ---- 4b. transpose V heads: VT[b][h][d][k]
        {
            dim3 gt(Lk / 32, DS / 32, BATCH);
            transpose_vh<<<gt, dim3(32, 8)>>>(VHi, VT, Lk);
        }

        // ---- 5. scores = (QH @ KH^T) / sqrt(hd)   batched over B*NH heads
        dim3 gs(Lk / BN, SEQ / BM, BATCH * NH);
        gemm_bf16x2<<<gs, blk, GEMM_SMEM>>>(QHi, KHi, nullptr, Sb,
                                            SEQ, Lk, HD, DS, DS, Lk,
                                            (long long)SEQ * DS, HD,
                                            (long long)Lk * DS,  HD,
                                            (long long)NH * SEQ * Lk, (long long)SEQ * Lk,
                                            NH, alpha_s);

        // ---- 6. row softmax (in place)
        dim3 gsm(SEQ, BATCH * NH);
        softmax_kernel<<<gsm, 256>>>(Sb, Lk);

        // ---- 7. weights0 = mean over heads (scale 0 only)
        if (i == 0 && (long long)out_size >= (long long)MROWS * HID + (long long)BATCH * SEQ * SEQ) {
            long long tot = (long long)BATCH * SEQ * SEQ;
            meanw_kernel<<<(unsigned)((tot + 255) / 256), 256>>>(Sb, out + (long long)MROWS * HID);
        }

        // ---- 8. OH = P @ VH  (via transposed V: TB GEMM, N=HD)
        dim3 go(HD / BN, SEQ / BM, BATCH * NH);
        gemm_bf16x2<<<go, blk, GEMM_SMEM>>>(Sb, VT, nullptr, OH,
                                            SEQ, HD, Lk, Lk, Lk, DS,
                                            (long long)NH * SEQ * Lk, (long long)SEQ * Lk,
                                            (long long)DS * Lk, (long long)HD * Lk,
                                            (long long)SEQ * DS, HD,
                                            NH, 1.f);

        // ---- 9. out projection into concat buffer column block i
        dim3 gp(DS / BN, MROWS / BM, 1);
        gemm_bf16x2<<<gp, blk, GEMM_SMEM>>>(OH, out_w + (long long)i * DS * DS, out_b + i * DS,
                                            ATT + i * DS,
                                            MROWS, DS, DS, DS, DS, HID,
                                            0, 0, 0, 0, 0, 0, 1, 1.f);
    }

    // ---- 10. fusion: out = ATT @ fus_w^T + fus_b
    gemm_bf16x2<<<g1, blk, GEMM_SMEM>>>(ATT, fus_w, fus_b, out, MROWS, HID, HID, HID, HID, HID,
                                        0, 0, 0, 0, 0, 0, 1, 1.f);
}

// round 5
// speedup vs baseline: 1.4471x; 1.4471x over previous
#include <cuda_runtime.h>
#include <cuda_bf16.h>
#include <math.h>
#include <stdint.h>

// ---------------- problem constants ----------------
#define BATCH   4
#define SEQ     2048
#define HID     1024
#define DS      256
#define NH      2
#define HD      128
#define MROWS   (BATCH*SEQ)  // 8192
typedef long long ll;

// ---------------- scratch (device globals; no allocation allowed) ----------------
// fp32 scratch
__device__ __align__(16) float g_K[MROWS*HID];
__device__ __align__(16) float g_V[MROWS*HID];
__device__ __align__(16) float g_S[BATCH*NH*SEQ*SEQ];   // 33.5M floats
// bf16 hi/lo planes
__device__ __align__(16) __nv_bfloat16 g_Xqh[MROWS*HID], g_Xql[MROWS*HID];  // split inputs
__device__ __align__(16) __nv_bfloat16 g_Xkh[MROWS*HID], g_Xkl[MROWS*HID];
__device__ __align__(16) __nv_bfloat16 g_Xvh[MROWS*HID], g_Xvl[MROWS*HID];
__device__ __align__(16) __nv_bfloat16 g_Qh [MROWS*HID], g_Ql [MROWS*HID];
__device__ __align__(16) __nv_bfloat16 g_Kh [MROWS*HID], g_Kl [MROWS*HID];
__device__ __align__(16) __nv_bfloat16 g_Vh [MROWS*HID], g_Vl [MROWS*HID];
__device__ __align__(16) __nv_bfloat16 g_QHh[MROWS*DS],  g_QHl[MROWS*DS];
__device__ __align__(16) __nv_bfloat16 g_KHh[MROWS*DS],  g_KHl[MROWS*DS];
__device__ __align__(16) __nv_bfloat16 g_VHh[MROWS*DS],  g_VHl[MROWS*DS];
__device__ __align__(16) __nv_bfloat16 g_VTh[MROWS*DS],  g_VTl[MROWS*DS];
__device__ __align__(16) __nv_bfloat16 g_KPh[BATCH*(SEQ/2)*DS], g_KPl[BATCH*(SEQ/2)*DS];
__device__ __align__(16) __nv_bfloat16 g_VPh[BATCH*(SEQ/2)*DS], g_VPl[BATCH*(SEQ/2)*DS];
__device__ __align__(16) __nv_bfloat16 g_Ph [BATCH*NH*SEQ*SEQ], g_Pl[BATCH*NH*SEQ*SEQ];
__device__ __align__(16) __nv_bfloat16 g_OHh[MROWS*DS],  g_OHl[MROWS*DS];
__device__ __align__(16) __nv_bfloat16 g_ATTh[MROWS*HID], g_ATTl[MROWS*HID];
// split weights
__device__ __align__(16) __nv_bfloat16 g_wqh[HID*HID], g_wql[HID*HID];
__device__ __align__(16) __nv_bfloat16 g_wkh[HID*HID], g_wkl[HID*HID];
__device__ __align__(16) __nv_bfloat16 g_wvh[HID*HID], g_wvl[HID*HID];
__device__ __align__(16) __nv_bfloat16 g_iwh[4*3*DS*DS], g_iwl[4*3*DS*DS];
__device__ __align__(16) __nv_bfloat16 g_owh[4*DS*DS],   g_owl[4*DS*DS];
__device__ __align__(16) __nv_bfloat16 g_fwh[HID*HID],   g_fwl[HID*HID];

// ---------------- helpers ----------------
__device__ __forceinline__ uint32_t smem_u32(const void* p) {
    uint32_t a;
    asm("{ .reg .u64 t; cvta.to.shared.u64 t, %1; cvt.u32.u64 %0, t; }" : "=r"(a) : "l"(p));
    return a;
}
__device__ __forceinline__ void ldm4(uint32_t* r, uint32_t addr) {
    asm volatile("ldmatrix.sync.aligned.m8n8.x4.shared.b16 {%0,%1,%2,%3}, [%4];"
                 : "=r"(r[0]), "=r"(r[1]), "=r"(r[2]), "=r"(r[3]) : "r"(addr));
}
__device__ __forceinline__ void mma_bf16(float* c, const uint32_t* a, uint32_t b0, uint32_t b1) {
    asm volatile("mma.sync.aligned.m16n8k16.row.col.f32.bf16.bf16.f32 "
                 "{%0,%1,%2,%3},{%4,%5,%6,%7},{%8,%9},{%0,%1,%2,%3};"
                 : "+f"(c[0]), "+f"(c[1]), "+f"(c[2]), "+f"(c[3])
                 : "r"(a[0]), "r"(a[1]), "r"(a[2]), "r"(a[3]), "r"(b0), "r"(b1));
}
__device__ __forceinline__ void cp16(uint32_t dst, const void* src) {
    asm volatile("cp.async.ca.shared.global [%0], [%1], 16;" :: "r"(dst), "l"(src));
}

// ---------------- split fp32 -> bf16 hi/lo ----------------
__global__ void split_kernel(const float* __restrict__ X,
                             __nv_bfloat16* __restrict__ H, __nv_bfloat16* __restrict__ L, ll n)
{
    ll i = ((ll)blockIdx.x * blockDim.x + threadIdx.x) * 4;
    if (i >= n) return;
    float4 v = *(const float4*)(X + i);
    float va[4] = {v.x, v.y, v.z, v.w};
    union Pk { __nv_bfloat16 b[4]; uint2 u; } h, l;
#pragma unroll
    for (int j = 0; j < 4; j++) {
        __nv_bfloat16 hh = __float2bfloat16(va[j]);
        h.b[j] = hh;
        l.b[j] = __float2bfloat16(va[j] - __bfloat162float(hh));
    }
    *(uint2*)(H + i) = h.u;
    *(uint2*)(L + i) = l.u;
}

// ---------------- pre-split tensor-core GEMM (cp.async, 4 stages) ----------------
// C = alpha * A @ B^T + bias.  A,B given as bf16 hi/lo planes.
// M, N multiples of 128; K multiple of 32, K >= 128.
#define BM 128
#define BN 128
#define BKS 32
#define LDT 40
#define MAT_BYTES (BM*LDT*2)            // 10240
#define STAGE_BYTES (4*MAT_BYTES)       // 40960
#define NSTAGE 4
#define GEMM_SMEM (NSTAGE*STAGE_BYTES)  // 163840

__global__ void __launch_bounds__(256)
gemm_pre(const __nv_bfloat16* __restrict__ Ah, const __nv_bfloat16* __restrict__ Al,
         const __nv_bfloat16* __restrict__ Bh, const __nv_bfloat16* __restrict__ Bl,
         const float* __restrict__ bias,
         float* __restrict__ Cf, __nv_bfloat16* __restrict__ Ch, __nv_bfloat16* __restrict__ Cl,
         int M, int N, int K, int lda, int ldb, int ldc,
         ll sAb, ll sAh_, ll sBb, ll sBh_, ll sCb, ll sCh_, int nh, float alpha)
{
    int z = blockIdx.z;
    int bb = z / nh, hh = z - bb * nh;
    ll offA = (ll)bb * sAb + (ll)hh * sAh_;
    ll offB = (ll)bb * sBb + (ll)hh * sBh_;
    ll offC = (ll)bb * sCb + (ll)hh * sCh_;
    Ah += offA; Al += offA; Bh += offB; Bl += offB;
    if (Cf) Cf += offC;
    if (Ch) { Ch += offC; Cl += offC; }

    extern __shared__ char smraw[];
    const uint32_t sbase = smem_u32(smraw);

    const int tid  = threadIdx.x;
    const int lane = tid & 31;
    const int wid  = tid >> 5;
    const int warpM = wid & 3;           // 4 warps in m (32 rows)
    const int warpN = wid >> 2;          // 2 warps in n (64 cols)
    const int row0 = blockIdx.y * BM;
    const int col0 = blockIdx.x * BN;

    const int r0  = tid >> 2;            // 0..63
    const int c16 = tid & 3;             // 16B chunk in k

    const int aRow = warpM * 32 + (lane & 7) + ((lane >> 3) & 1) * 8;
    const int aCol = (lane >> 4) * 8;
    const int bRow = warpN * 64 + (lane & 7) + (lane >> 4) * 8;
    const int bCol = ((lane >> 3) & 1) * 8;
    uint32_t aOff[2], bOff[4];
#pragma unroll
    for (int mi = 0; mi < 2; mi++) aOff[mi] = (uint32_t)(((aRow + mi * 16) * LDT + aCol) * 2);
#pragma unroll
    for (int p = 0; p < 4; p++)    bOff[p] = (uint32_t)(((bRow + p * 16) * LDT + bCol) * 2);

    float acc[2][8][4];
#pragma unroll
    for (int mi = 0; mi < 2; mi++)
#pragma unroll
        for (int na = 0; na < 8; na++)
#pragma unroll
            for (int q = 0; q < 4; q++) acc[mi][na][q] = 0.f;

    auto issue = [&](int k0, int st) {
        uint32_t dbase = sbase + st * STAGE_BYTES;
#pragma unroll
        for (int it = 0; it < 2; it++) {
            int row = r0 + it * 64;
            ll aoff = (ll)(row0 + row) * lda + k0 + c16 * 8;
            ll boff = (ll)(col0 + row) * ldb + k0 + c16 * 8;
            uint32_t doff = (uint32_t)(row * (LDT * 2) + c16 * 16);
            cp16(dbase + 0 * MAT_BYTES + doff, Ah + aoff);
            cp16(dbase + 1 * MAT_BYTES + doff, Al + aoff);
            cp16(dbase + 2 * MAT_BYTES + doff, Bh + boff);
            cp16(dbase + 3 * MAT_BYTES + doff, Bl + boff);
        }
    };

    const int KT = K / BKS;
    issue(0 * BKS, 0); asm volatile("cp.async.commit_group;" ::: "memory");
    issue(1 * BKS, 1); asm volatile("cp.async.commit_group;" ::: "memory");
    issue(2 * BKS, 2); asm volatile("cp.async.commit_group;" ::: "memory");

    for (int kt = 0; kt < KT; kt++) {
        asm volatile("cp.async.wait_group 2;" ::: "memory");
        __syncthreads();
        if (kt + 3 < KT) issue((kt + 3) * BKS, (kt + 3) & 3);
        asm volatile("cp.async.commit_group;" ::: "memory");

        const int st = kt & 3;
        const uint32_t bAh = sbase + st * STAGE_BYTES;
        const uint32_t bAl = bAh + MAT_BYTES;
        const uint32_t bBh = bAh + 2 * MAT_BYTES;
        const uint32_t bBl = bAh + 3 * MAT_BYTES;

#pragma unroll
        for (int ka = 0; ka < BKS; ka += 16) {
            uint32_t ahf[2][4], alf[2][4];
#pragma unroll
            for (int mi = 0; mi < 2; mi++) {
                ldm4(ahf[mi], bAh + aOff[mi] + ka * 2);
                ldm4(alf[mi], bAl + aOff[mi] + ka * 2);
            }
#pragma unroll
            for (int p = 0; p < 4; p++) {
                uint32_t bhf[4], blf[4];
                ldm4(bhf, bBh + bOff[p] + ka * 2);
                ldm4(blf, bBl + bOff[p] + ka * 2);
#pragma unroll
                for (int mi = 0; mi < 2; mi++)
#pragma unroll
                    for (int s = 0; s < 2; s++) {
                        int na = p * 2 + s;
                        mma_bf16(acc[mi][na], ahf[mi], bhf[2 * s], bhf[2 * s + 1]);
                        mma_bf16(acc[mi][na], ahf[mi], blf[2 * s], blf[2 * s + 1]);
                        mma_bf16(acc[mi][na], alf[mi], bhf[2 * s], bhf[2 * s + 1]);
                    }
            }
        }
    }

    // epilogue
    const int crow  = row0 + warpM * 32 + (lane >> 2);
    const int ccol0 = col0 + warpN * 64 + (lane & 3) * 2;
#pragma unroll
    for (int mi = 0; mi < 2; mi++) {
#pragma unroll
        for (int na = 0; na < 8; na++) {
            int r = crow + mi * 16;
            int c = ccol0 + na * 8;
            float b0 = bias ? bias[c]     : 0.f;
            float b1 = bias ? bias[c + 1] : 0.f;
            float v00 = acc[mi][na][0] * alpha + b0;
            float v01 = acc[mi][na][1] * alpha + b1;
            float v10 = acc[mi][na][2] * alpha + b0;
            float v11 = acc[mi][na][3] * alpha + b1;
            if (Cf) {
                *(float2*)&Cf[(ll)r * ldc + c]       = make_float2(v00, v01);
                *(float2*)&Cf[(ll)(r + 8) * ldc + c] = make_float2(v10, v11);
            }
            if (Ch) {
                __nv_bfloat162 h0, l0, h1, l1;
                h0.x = __float2bfloat16(v00); h0.y = __float2bfloat16(v01);
                l0.x = __float2bfloat16(v00 - __bfloat162float(h0.x));
                l0.y = __float2bfloat16(v01 - __bfloat162float(h0.y));
                h1.x = __float2bfloat16(v10); h1.y = __float2bfloat16(v11);
                l1.x = __float2bfloat16(v10 - __bfloat162float(h1.x));
                l1.y = __float2bfloat16(v11 - __bfloat162float(h1.y));
                *(__nv_bfloat162*)&Ch[(ll)r * ldc + c]       = h0;
                *(__nv_bfloat162*)&Cl[(ll)r * ldc + c]       = l0;
                *(__nv_bfloat162*)&Ch[(ll)(r + 8) * ldc + c] = h1;
                *(__nv_bfloat162*)&Cl[(ll)(r + 8) * ldc + c] = l1;
            }
        }
    }
}

// ---------------- avg-pool of a DS-wide column slice -> hi/lo planes ----------------
__global__ void pool_kernel(const float* __restrict__ X,
                            __nv_bfloat16* __restrict__ YH, __nv_bfloat16* __restrict__ YL,
                            int rows, int s, int colOff)
{
    int idx = blockIdx.x * blockDim.x + threadIdx.x;
    int total = rows * DS;
    if (idx >= total) return;
    int r = idx / DS, c = idx - r * DS;
    const float* src = X + (ll)r * s * HID + colOff + c;
    float acc = 0.f;
    for (int j = 0; j < s; j++) acc += src[(ll)j * HID];
    float v = acc * (1.f / s);
    __nv_bfloat16 h = __float2bfloat16(v);
    YH[idx] = h;
    YL[idx] = __float2bfloat16(v - __bfloat162float(h));
}

// ---------------- transpose one bf16 plane: X [B][Lk][DS] -> Y [B][NH][HD][Lk] ----------------
__global__ void transpose_vh(const __nv_bfloat16* __restrict__ X, __nv_bfloat16* __restrict__ Y, int Lk)
{
    __shared__ __nv_bfloat16 t[32][34];
    int b  = blockIdx.z;
    int k0 = blockIdx.x * 32, d0 = blockIdx.y * 32;
    int tx = threadIdx.x, ty = threadIdx.y;   // 32 x 8
#pragma unroll
    for (int j = 0; j < 32; j += 8)
        t[ty + j][tx] = X[((ll)b * Lk + k0 + ty + j) * DS + d0 + tx];
    __syncthreads();
    int head = d0 >> 7;
    int dh0  = d0 & 127;
#pragma unroll
    for (int j = 0; j < 32; j += 8) {
        int d = dh0 + ty + j;
        Y[(ll)b * DS * Lk + (ll)head * HD * Lk + (ll)d * Lk + k0 + tx] = t[tx][ty + j];
    }
}

// ---------------- row softmax: fp32 scores -> bf16 hi/lo prob planes ----------------
__global__ void softmax_kernel(float* __restrict__ S,
                               __nv_bfloat16* __restrict__ PH, __nv_bfloat16* __restrict__ PL, int Lk)
{
    ll row = (ll)blockIdx.y * gridDim.x + blockIdx.x;
    float* p = S + row * Lk;
    __nv_bfloat16* ph = PH + row * Lk;
    __nv_bfloat16* pl = PL + row * Lk;
    __shared__ float red[256];
    int tid = threadIdx.x;

    float m = -1e30f;
    for (int i = tid; i < Lk; i += 256) m = fmaxf(m, p[i]);
    red[tid] = m; __syncthreads();
    for (int s = 128; s > 0; s >>= 1) {
        if (tid < s) red[tid] = fmaxf(red[tid], red[tid + s]);
        __syncthreads();
    }
    m = red[0]; __syncthreads();

    float sum = 0.f;
    for (int i = tid; i < Lk; i += 256) {
        float e = __expf(p[i] - m);
        p[i] = e; sum += e;
    }
    red[tid] = sum; __syncthreads();
    for (int s = 128; s > 0; s >>= 1) {
        if (tid < s) red[tid] += red[tid + s];
        __syncthreads();
    }
    float inv = 1.f / red[0];
    for (int i = tid; i < Lk; i += 256) {
        float v = p[i] * inv;
        __nv_bfloat16 h = __float2bfloat16(v);
        ph[i] = h;
        pl[i] = __float2bfloat16(v - __bfloat162float(h));
    }
}

// ---------------- weights0 = mean of 2 heads from hi/lo prob planes ----------------
__global__ void meanw_kernel(const __nv_bfloat16* __restrict__ PH,
                             const __nv_bfloat16* __restrict__ PL, float* __restrict__ W)
{
    ll idx = (ll)blockIdx.x * blockDim.x + threadIdx.x;
    const ll per = (ll)SEQ * SEQ;
    const ll total = (ll)BATCH * per;
    if (idx >= total) return;
    ll b = idx / per, rest = idx - b * per;
    ll i0 = (b * 2 + 0) * per + rest;
    ll i1 = (b * 2 + 1) * per + rest;
    float v0 = __bfloat162float(PH[i0]) + __bfloat162float(PL[i0]);
    float v1 = __bfloat162float(PH[i1]) + __bfloat162float(PL[i1]);
    W[idx] = 0.5f * (v0 + v1);
}

// ---------------- host orchestration ----------------
static inline void launch_split(const float* x, __nv_bfloat16* h, __nv_bfloat16* l, ll n)
{
    ll threads = (n + 3) / 4;
    split_kernel<<<(unsigned)((threads + 255) / 256), 256>>>(x, h, l, n);
}

extern "C" void kernel_launch(void* const* d_in, const int* in_sizes, int n_in,
                              void* d_out, int out_size)
{
    const float* query = (const float*)d_in[0];
    const float* key_  = (const float*)d_in[1];
    const float* value = (const float*)d_in[2];
    const float* wq    = (const float*)d_in[3];
    const float* bq    = (const float*)d_in[4];
    const float* wk    = (const float*)d_in[5];
    const float* bk    = (const float*)d_in[6];
    const float* wv    = (const float*)d_in[7];
    const float* bv    = (const float*)d_in[8];
    const float* in_w  = (const float*)d_in[9];
    const float* in_b  = (const float*)d_in[10];
    const float* out_w = (const float*)d_in[11];
    const float* out_b = (const float*)d_in[12];
    const float* fus_w = (const float*)d_in[13];
    const float* fus_b = (const float*)d_in[14];
    float* out = (float*)d_out;

    float *K, *V, *Sb;
    __nv_bfloat16 *Xqh,*Xql,*Xkh,*Xkl,*Xvh,*Xvl, *Qh,*Ql,*Kh,*Kl,*Vh,*Vl;
    __nv_bfloat16 *QHh,*QHl,*KHh,*KHl,*VHh,*VHl,*VTh,*VTl;
    __nv_bfloat16 *KPh,*KPl,*VPh,*VPl,*Ph,*Pl,*OHh,*OHl,*ATTh,*ATTl;
    __nv_bfloat16 *wqh,*wql,*wkh,*wkl,*wvh,*wvl,*iwh,*iwl,*owh,*owl,*fwh,*fwl;
    cudaGetSymbolAddress((void**)&K,  g_K);   cudaGetSymbolAddress((void**)&V,  g_V);
    cudaGetSymbolAddress((void**)&Sb, g_S);
    cudaGetSymbolAddress((void**)&Xqh, g_Xqh); cudaGetSymbolAddress((void**)&Xql, g_Xql);
    cudaGetSymbolAddress((void**)&Xkh, g_Xkh); cudaGetSymbolAddress((void**)&Xkl, g_Xkl);
    cudaGetSymbolAddress((void**)&Xvh, g_Xvh); cudaGetSymbolAddress((void**)&Xvl, g_Xvl);
    cudaGetSymbolAddress((void**)&Qh,  g_Qh);  cudaGetSymbolAddress((void**)&Ql,  g_Ql);
    cudaGetSymbolAddress((void**)&Kh,  g_Kh);  cudaGetSymbolAddress((void**)&Kl,  g_Kl);
    cudaGetSymbolAddress((void**)&Vh,  g_Vh);  cudaGetSymbolAddress((void**)&Vl,  g_Vl);
    cudaGetSymbolAddress((void**)&QHh, g_QHh); cudaGetSymbolAddress((void**)&QHl, g_QHl);
    cudaGetSymbolAddress((void**)&KHh, g_KHh); cudaGetSymbolAddress((void**)&KHl, g_KHl);
    cudaGetSymbolAddress((void**)&VHh, g_VHh); cudaGetSymbolAddress((void**)&VHl, g_VHl);
    cudaGetSymbolAddress((void**)&VTh, g_VTh); cudaGetSymbolAddress((void**)&VTl, g_VTl);
    cudaGetSymbolAddress((void**)&KPh, g_KPh); cudaGetSymbolAddress((void**)&KPl, g_KPl);
    cudaGetSymbolAddress((void**)&VPh, g_VPh); cudaGetSymbolAddress((void**)&VPl, g_VPl);
    cudaGetSymbolAddress((void**)&Ph,  g_Ph);  cudaGetSymbolAddress((void**)&Pl,  g_Pl);
    cudaGetSymbolAddress((void**)&OHh, g_OHh); cudaGetSymbolAddress((void**)&OHl, g_OHl);
    cudaGetSymbolAddress((void**)&ATTh,g_ATTh);cudaGetSymbolAddress((void**)&ATTl,g_ATTl);
    cudaGetSymbolAddress((void**)&wqh, g_wqh); cudaGetSymbolAddress((void**)&wql, g_wql);
    cudaGetSymbolAddress((void**)&wkh, g_wkh); cudaGetSymbolAddress((void**)&wkl, g_wkl);
    cudaGetSymbolAddress((void**)&wvh, g_wvh); cudaGetSymbolAddress((void**)&wvl, g_wvl);
    cudaGetSymbolAddress((void**)&iwh, g_iwh); cudaGetSymbolAddress((void**)&iwl, g_iwl);
    cudaGetSymbolAddress((void**)&owh, g_owh); cudaGetSymbolAddress((void**)&owl, g_owl);
    cudaGetSymbolAddress((void**)&fwh, g_fwh); cudaGetSymbolAddress((void**)&fwl, g_fwl);

    cudaFuncSetAttribute(gemm_pre, cudaFuncAttributeMaxDynamicSharedMemorySize, GEMM_SMEM);

    const dim3 blk(256);
    const float alpha_s = 0.08838834764831845f;   // 1/sqrt(128)
    const int scales[4] = {1, 2, 4, 8};

    // ---- 0. split inputs + weights into bf16 hi/lo planes
    launch_split(query, Xqh, Xql, (ll)MROWS * HID);
    launch_split(key_,  Xkh, Xkl, (ll)MROWS * HID);
    launch_split(value, Xvh, Xvl, (ll)MROWS * HID);
    launch_split(wq, wqh, wql, (ll)HID * HID);
    launch_split(wk, wkh, wkl, (ll)HID * HID);
    launch_split(wv, wvh, wvl, (ll)HID * HID);
    launch_split(in_w,  iwh, iwl, (ll)4 * 3 * DS * DS);
    launch_split(out_w, owh, owl, (ll)4 * DS * DS);
    launch_split(fus_w, fwh, fwl, (ll)HID * HID);

    // ---- 1. input projections
    dim3 g1(HID / BN, MROWS / BM, 1);
    gemm_pre<<<g1, blk, GEMM_SMEM>>>(Xqh, Xql, wqh, wql, bq, nullptr, Qh, Ql,
                                     MROWS, HID, HID, HID, HID, HID,
                                     0, 0, 0, 0, 0, 0, 1, 1.f);
    gemm_pre<<<g1, blk, GEMM_SMEM>>>(Xkh, Xkl, wkh, wkl, bk, K, Kh, Kl,
                                     MROWS, HID, HID, HID, HID, HID,
                                     0, 0, 0, 0, 0, 0, 1, 1.f);
    gemm_pre<<<g1, blk, GEMM_SMEM>>>(Xvh, Xvl, wvh, wvl, bv, V, Vh, Vl,
                                     MROWS, HID, HID, HID, HID, HID,
                                     0, 0, 0, 0, 0, 0, 1, 1.f);

    for (int i = 0; i < 4; i++) {
        const int s  = scales[i];
        const int Lk = SEQ / s;
        const int Mk = BATCH * Lk;
        const ll wOff = (ll)i * 3 * DS * DS;
        const float* bi = in_b + (ll)i * 3 * DS;

        // ---- 2. q head projection (A = Q columns slice)
        dim3 gq(DS / BN, MROWS / BM, 1);
        gemm_pre<<<gq, blk, GEMM_SMEM>>>(Qh + i * DS, Ql + i * DS, iwh + wOff, iwl + wOff,
                                         bi, nullptr, QHh, QHl,
                                         MROWS, DS, DS, HID, DS, DS,
                                         0, 0, 0, 0, 0, 0, 1, 1.f);

        // ---- 3. pooled k/v sources
        const __nv_bfloat16 *kAh, *kAl, *vAh, *vAl; int pl;
        if (s == 1) { kAh = Kh + i * DS; kAl = Kl + i * DS; vAh = Vh + i * DS; vAl = Vl + i * DS; pl = HID; }
        else {
            int total = Mk * DS;
            pool_kernel<<<(total + 255) / 256, 256>>>(K, KPh, KPl, Mk, s, i * DS);
            pool_kernel<<<(total + 255) / 256, 256>>>(V, VPh, VPl, Mk, s, i * DS);
            kAh = KPh; kAl = KPl; vAh = VPh; vAl = VPl; pl = DS;
        }

        // ---- 4. k/v head projections
        dim3 gk(DS / BN, Mk / BM, 1);
        gemm_pre<<<gk, blk, GEMM_SMEM>>>(kAh, kAl, iwh + wOff + DS * DS, iwl + wOff + DS * DS,
                                         bi + DS, nullptr, KHh, KHl,
                                         Mk, DS, DS, pl, DS, DS,
                                         0, 0, 0, 0, 0, 0, 1, 1.f);
        gemm_pre<<<gk, blk, GEMM_SMEM>>>(vAh, vAl, iwh + wOff + 2 * DS * DS, iwl + wOff + 2 * DS * DS,
                                         bi + 2 * DS, nullptr, VHh, VHl,
                                         Mk, DS, DS, pl, DS, DS,
                                         0, 0, 0, 0, 0, 0, 1, 1.f);

        // ---- 4b. transpose V heads (both planes)
        {
            dim3 gt(Lk / 32, DS / 32, BATCH);
            transpose_vh<<<gt, dim3(32, 8)>>>(VHh, VTh, Lk);
            transpose_vh<<<gt, dim3(32, 8)>>>(VHl, VTl, Lk);
        }

        // ---- 5. scores = (QH @ KH^T) / sqrt(hd), batched over B*NH
        dim3 gs(Lk / BN, SEQ / BM, BATCH * NH);
        gemm_pre<<<gs, blk, GEMM_SMEM>>>(QHh, QHl, KHh, KHl, nullptr, Sb, nullptr, nullptr,
                                         SEQ, Lk, HD, DS, DS, Lk,
                                         (ll)SEQ * DS, HD, (ll)Lk * DS, HD,
                                         (ll)NH * SEQ * Lk, (ll)SEQ * Lk,
                                         NH, alpha_s);

        // ---- 6. softmax -> hi/lo prob planes
        dim3 gsm(SEQ, BATCH * NH);
        softmax_kernel<<<gsm, 256>>>(Sb, Ph, Pl, Lk);

        // ---- 7. weights0 (scale 0 only)
        if (i == 0 && (ll)out_size >= (ll)MROWS * HID + (ll)BATCH * SEQ * SEQ) {
            ll tot = (ll)BATCH * SEQ * SEQ;
            meanw_kernel<<<(unsigned)((tot + 255) / 256), 256>>>(Ph, Pl, out + (ll)MROWS * HID);
        }

        // ---- 8. OH = P @ VH (via transposed V)
        dim3 go(HD / BN, SEQ / BM, BATCH * NH);
        gemm_pre<<<go, blk, GEMM_SMEM>>>(Ph, Pl, VTh, VTl, nullptr, nullptr, OHh, OHl,
                                         SEQ, HD, Lk, Lk, Lk, DS,
                                         (ll)NH * SEQ * Lk, (ll)SEQ * Lk,
                                         (ll)DS * Lk, (ll)HD * Lk,
                                         (ll)SEQ * DS, HD,
                                         NH, 1.f);

        // ---- 9. out projection into concat buffer column block i
        dim3 gp(DS / BN, MROWS / BM, 1);
        gemm_pre<<<gp, blk, GEMM_SMEM>>>(OHh, OHl, owh + (ll)i * DS * DS, owl + (ll)i * DS * DS,
                                         out_b + i * DS, nullptr, ATTh + i * DS, ATTl + i * DS,
                                         MROWS, DS, DS, DS, DS, HID,
                                         0, 0, 0, 0, 0, 0, 1, 1.f);
    }

    // ---- 10. fusion: out = ATT @ fus_w^T + fus_b
    gemm_pre<<<g1, blk, GEMM_SMEM>>>(ATTh, ATTl, fwh, fwl, fus_b, out, nullptr, nullptr,
                                     MROWS, HID, HID, HID, HID, HID,
                                     0, 0, 0, 0, 0, 0, 1, 1.f);
}

// round 7
// speedup vs baseline: 1.5541x; 1.0740x over previous
#include <cuda_runtime.h>
#include <cuda_bf16.h>
#include <math.h>
#include <stdint.h>

// ---------------- problem constants ----------------
#define BATCH   4
#define SEQ     2048
#define HID     1024
#define DS      256
#define NH      2
#define HD      128
#define MROWS   (BATCH*SEQ)      // 8192
#define PSTR    (MROWS*DS)       // per-scale plane stride (2M elems)
typedef long long ll;

// per-scale tables
#define LK0 2048
#define LK1 1024
#define LK2 512
#define LK3 256
__device__ __constant__ int d_LK[4]   = {2048, 1024, 512, 256};
// S offsets (elements): 16384*Lk per scale
#define SOFF0 0LL
#define SOFF1 33554432LL
#define SOFF2 50331648LL
#define SOFF3 58720256LL
#define STOT  62914560LL
__device__ __constant__ ll d_SOFF[4] = {SOFF0, SOFF1, SOFF2, SOFF3};

// ---------------- scratch (device globals; no allocation allowed) ----------------
__device__ __align__(16) float g_S[STOT];
__device__ __align__(16) __nv_bfloat16 g_Ph[STOT], g_Pl[STOT];
__device__ __align__(16) __nv_bfloat16 g_Xqh[MROWS*HID], g_Xql[MROWS*HID];
__device__ __align__(16) __nv_bfloat16 g_Xkh[MROWS*HID], g_Xkl[MROWS*HID];
__device__ __align__(16) __nv_bfloat16 g_Xvh[MROWS*HID], g_Xvl[MROWS*HID];
__device__ __align__(16) __nv_bfloat16 g_Qh [MROWS*HID], g_Ql [MROWS*HID];
__device__ __align__(16) __nv_bfloat16 g_Kh [MROWS*HID], g_Kl [MROWS*HID];
__device__ __align__(16) __nv_bfloat16 g_Vh [MROWS*HID], g_Vl [MROWS*HID];
__device__ __align__(16) __nv_bfloat16 g_QHh[4*PSTR], g_QHl[4*PSTR];
__device__ __align__(16) __nv_bfloat16 g_KHh[4*PSTR], g_KHl[4*PSTR];
__device__ __align__(16) __nv_bfloat16 g_VHh[4*PSTR], g_VHl[4*PSTR];
__device__ __align__(16) __nv_bfloat16 g_VTh[4*PSTR], g_VTl[4*PSTR];
__device__ __align__(16) __nv_bfloat16 g_OHh[4*PSTR], g_OHl[4*PSTR];
__device__ __align__(16) __nv_bfloat16 g_KPh[1835008], g_KPl[1835008];
__device__ __align__(16) __nv_bfloat16 g_VPh[1835008], g_VPl[1835008];
__device__ __align__(16) __nv_bfloat16 g_ATTh[MROWS*HID], g_ATTl[MROWS*HID];
__device__ __align__(16) __nv_bfloat16 g_wqh[HID*HID], g_wql[HID*HID];
__device__ __align__(16) __nv_bfloat16 g_wkh[HID*HID], g_wkl[HID*HID];
__device__ __align__(16) __nv_bfloat16 g_wvh[HID*HID], g_wvl[HID*HID];
__device__ __align__(16) __nv_bfloat16 g_iwh[4*3*DS*DS], g_iwl[4*3*DS*DS];
__device__ __align__(16) __nv_bfloat16 g_owh[4*DS*DS],   g_owl[4*DS*DS];
__device__ __align__(16) __nv_bfloat16 g_fwh[HID*HID],   g_fwl[HID*HID];

// ---------------- helpers ----------------
__device__ __forceinline__ uint32_t smem_u32(const void* p) {
    uint32_t a;
    asm("{ .reg .u64 t; cvta.to.shared.u64 t, %1; cvt.u32.u64 %0, t; }" : "=r"(a) : "l"(p));
    return a;
}
__device__ __forceinline__ void ldm4(uint32_t* r, uint32_t addr) {
    asm volatile("ldmatrix.sync.aligned.m8n8.x4.shared.b16 {%0,%1,%2,%3}, [%4];"
                 : "=r"(r[0]), "=r"(r[1]), "=r"(r[2]), "=r"(r[3]) : "r"(addr));
}
__device__ __forceinline__ void mma_bf16(float* c, const uint32_t* a, uint32_t b0, uint32_t b1) {
    asm volatile("mma.sync.aligned.m16n8k16.row.col.f32.bf16.bf16.f32 "
                 "{%0,%1,%2,%3},{%4,%5,%6,%7},{%8,%9},{%0,%1,%2,%3};"
                 : "+f"(c[0]), "+f"(c[1]), "+f"(c[2]), "+f"(c[3])
                 : "r"(a[0]), "r"(a[1]), "r"(a[2]), "r"(a[3]), "r"(b0), "r"(b1));
}
__device__ __forceinline__ void cp16(uint32_t dst, const void* src) {
    asm volatile("cp.async.ca.shared.global [%0], [%1], 16;" :: "r"(dst), "l"(src));
}

// ---------------- batched GEMM parameter table ----------------
struct GArg {
    const __nv_bfloat16 *Ah, *Al, *Bh, *Bl;
    const float* bias;
    float* Cf;
    __nv_bfloat16 *Ch, *Cl;
    int M, N, K, lda, ldb, ldc;
    float alpha;
    int pad;
};
struct GTab { GArg a[32]; };

// ---------------- pre-split tensor-core GEMM (cp.async, 4-stage ring, 3 in flight) ----------------
#define BM 128
#define BN 128
#define BKS 32
#define LDT 40
#define MAT_BYTES (BM*LDT*2)
#define STAGE_BYTES (4*MAT_BYTES)
#define NSTAGE 4
#define GEMM_SMEM (NSTAGE*STAGE_BYTES)  // 163840

__global__ void __launch_bounds__(256)
gemm_pre(GTab tab)
{
    const GArg g = tab.a[blockIdx.z];
    const int row0 = blockIdx.y * BM;
    const int col0 = blockIdx.x * BN;
    if (row0 >= g.M || col0 >= g.N) return;

    const __nv_bfloat16 *Ah = g.Ah, *Al = g.Al, *Bh = g.Bh, *Bl = g.Bl;
    const int lda = g.lda, ldb = g.ldb, ldc = g.ldc, K = g.K;

    extern __shared__ char smraw[];
    const uint32_t sbase = smem_u32(smraw);

    const int tid  = threadIdx.x;
    const int lane = tid & 31;
    const int wid  = tid >> 5;
    const int warpM = wid & 3;
    const int warpN = wid >> 2;

    const int r0  = tid >> 2;
    const int c16 = tid & 3;

    const int aRow = warpM * 32 + (lane & 7) + ((lane >> 3) & 1) * 8;
    const int aCol = (lane >> 4) * 8;
    const int bRow = warpN * 64 + (lane & 7) + (lane >> 4) * 8;
    const int bCol = ((lane >> 3) & 1) * 8;
    uint32_t aOff[2], bOff[4];
#pragma unroll
    for (int mi = 0; mi < 2; mi++) aOff[mi] = (uint32_t)(((aRow + mi * 16) * LDT + aCol) * 2);
#pragma unroll
    for (int p = 0; p < 4; p++)    bOff[p] = (uint32_t)(((bRow + p * 16) * LDT + bCol) * 2);

    float acc[2][8][4];
#pragma unroll
    for (int mi = 0; mi < 2; mi++)
#pragma unroll
        for (int na = 0; na < 8; na++)
#pragma unroll
            for (int q = 0; q < 4; q++) acc[mi][na][q] = 0.f;

    auto issue = [&](int k0, int st) {
        uint32_t dbase = sbase + st * STAGE_BYTES;
#pragma unroll
        for (int it = 0; it < 2; it++) {
            int row = r0 + it * 64;
            ll aoff = (ll)(row0 + row) * lda + k0 + c16 * 8;
            ll boff = (ll)(col0 + row) * ldb + k0 + c16 * 8;
            uint32_t doff = (uint32_t)(row * (LDT * 2) + c16 * 16);
            cp16(dbase + 0 * MAT_BYTES + doff, Ah + aoff);
            cp16(dbase + 1 * MAT_BYTES + doff, Al + aoff);
            cp16(dbase + 2 * MAT_BYTES + doff, Bh + boff);
            cp16(dbase + 3 * MAT_BYTES + doff, Bl + boff);
        }
    };

    const int KT = K / BKS;
    issue(0 * BKS, 0); asm volatile("cp.async.commit_group;" ::: "memory");
    issue(1 * BKS, 1); asm volatile("cp.async.commit_group;" ::: "memory");
    issue(2 * BKS, 2); asm volatile("cp.async.commit_group;" ::: "memory");

    for (int kt = 0; kt < KT; kt++) {
        asm volatile("cp.async.wait_group %0;" :: "n"(NSTAGE - 2) : "memory");
        __syncthreads();
        if (kt + 3 < KT) issue((kt + 3) * BKS, (kt + 3) & 3);
        asm volatile("cp.async.commit_group;" ::: "memory");

        const int st = kt & 3;
        const uint32_t bAh = sbase + st * STAGE_BYTES;
        const uint32_t bAl = bAh + MAT_BYTES;
        const uint32_t bBh = bAh + 2 * MAT_BYTES;
        const uint32_t bBl = bAh + 3 * MAT_BYTES;

#pragma unroll
        for (int ka = 0; ka < BKS; ka += 16) {
            uint32_t ahf[2][4], alf[2][4];
#pragma unroll
            for (int mi = 0; mi < 2; mi++) {
                ldm4(ahf[mi], bAh + aOff[mi] + ka * 2);
                ldm4(alf[mi], bAl + aOff[mi] + ka * 2);
            }
#pragma unroll
            for (int p = 0; p < 4; p++) {
                uint32_t bhf[4], blf[4];
                ldm4(bhf, bBh + bOff[p] + ka * 2);
                ldm4(blf, bBl + bOff[p] + ka * 2);
#pragma unroll
                for (int mi = 0; mi < 2; mi++)
#pragma unroll
                    for (int s = 0; s < 2; s++) {
                        int na = p * 2 + s;
                        mma_bf16(acc[mi][na], ahf[mi], bhf[2 * s], bhf[2 * s + 1]);
                        mma_bf16(acc[mi][na], ahf[mi], blf[2 * s], blf[2 * s + 1]);
                        mma_bf16(acc[mi][na], alf[mi], bhf[2 * s], bhf[2 * s + 1]);
                    }
            }
        }
    }

    // epilogue
    const int crow  = row0 + warpM * 32 + (lane >> 2);
    const int ccol0 = col0 + warpN * 64 + (lane & 3) * 2;
#pragma unroll
    for (int mi = 0; mi < 2; mi++) {
#pragma unroll
        for (int na = 0; na < 8; na++) {
            int r = crow + mi * 16;
            int c = ccol0 + na * 8;
            float b0 = g.bias ? g.bias[c]     : 0.f;
            float b1 = g.bias ? g.bias[c + 1] : 0.f;
            float v00 = acc[mi][na][0] * g.alpha + b0;
            float v01 = acc[mi][na][1] * g.alpha + b1;
            float v10 = acc[mi][na][2] * g.alpha + b0;
            float v11 = acc[mi][na][3] * g.alpha + b1;
            if (g.Cf) {
                *(float2*)&g.Cf[(ll)r * ldc + c]       = make_float2(v00, v01);
                *(float2*)&g.Cf[(ll)(r + 8) * ldc + c] = make_float2(v10, v11);
            }
            if (g.Ch) {
                __nv_bfloat162 h0, l0, h1, l1;
                h0.x = __float2bfloat16(v00); h0.y = __float2bfloat16(v01);
                l0.x = __float2bfloat16(v00 - __bfloat162float(h0.x));
                l0.y = __float2bfloat16(v01 - __bfloat162float(h0.y));
                h1.x = __float2bfloat16(v10); h1.y = __float2bfloat16(v11);
                l1.x = __float2bfloat16(v10 - __bfloat162float(h1.x));
                l1.y = __float2bfloat16(v11 - __bfloat162float(h1.y));
                *(__nv_bfloat162*)&g.Ch[(ll)r * ldc + c]       = h0;
                *(__nv_bfloat162*)&g.Cl[(ll)r * ldc + c]       = l0;
                *(__nv_bfloat162*)&g.Ch[(ll)(r + 8) * ldc + c] = h1;
                *(__nv_bfloat162*)&g.Cl[(ll)(r + 8) * ldc + c] = l1;
            }
        }
    }
}

// ---------------- batched split fp32 -> bf16 hi/lo ----------------
struct SJob { const float* src; __nv_bfloat16* h; __nv_bfloat16* l; ll n; };
struct STab { SJob j[9]; };

__global__ void split_batch(STab t)
{
    SJob jb = t.j[blockIdx.y];
    ll i = ((ll)blockIdx.x * blockDim.x + threadIdx.x) * 4;
    if (i >= jb.n) return;
    float4 v = *(const float4*)(jb.src + i);
    float va[4] = {v.x, v.y, v.z, v.w};
    union Pk { __nv_bfloat16 b[4]; uint2 u; } h, l;
#pragma unroll
    for (int j = 0; j < 4; j++) {
        __nv_bfloat16 hh = __float2bfloat16(va[j]);
        h.b[j] = hh;
        l.b[j] = __float2bfloat16(va[j] - __bfloat162float(hh));
    }
    *(uint2*)(jb.h + i) = h.u;
    *(uint2*)(jb.l + i) = l.u;
}

// ---------------- batched avg-pool (reads hi/lo planes, writes hi/lo) ----------------
struct PJob { const __nv_bfloat16* xh; const __nv_bfloat16* xl;
              __nv_bfloat16* yh; __nv_bfloat16* yl; int rows; int s; int colOff; int pad; };
struct PTab { PJob j[6]; };

__global__ void pool_batch(PTab t)
{
    PJob jb = t.j[blockIdx.y];
    int idx = blockIdx.x * blockDim.x + threadIdx.x;
    int total = jb.rows * DS;
    if (idx >= total) return;
    int r = idx / DS, c = idx - r * DS;
    ll base = (ll)r * jb.s * HID + jb.colOff + c;
    float acc = 0.f;
    for (int j = 0; j < jb.s; j++) {
        ll o = base + (ll)j * HID;
        acc += __bfloat162float(jb.xh[o]) + __bfloat162float(jb.xl[o]);
    }
    float v = acc * (1.f / jb.s);
    __nv_bfloat16 h = __float2bfloat16(v);
    jb.yh[idx] = h;
    jb.yl[idx] = __float2bfloat16(v - __bfloat162float(h));
}

// ---------------- batched transpose: VH [b][Lk][DS] -> VT [b][NH][HD][Lk] ----------------
__global__ void transpose_batch(const __nv_bfloat16* __restrict__ VHhp,
                                const __nv_bfloat16* __restrict__ VHlp,
                                __nv_bfloat16* __restrict__ VThp,
                                __nv_bfloat16* __restrict__ VTlp)
{
    __shared__ __nv_bfloat16 t[32][34];
    int z  = blockIdx.z;
    int b  = z & 3;
    int s  = (z >> 2) & 3;
    int pl = z >> 4;
    int Lk = d_LK[s];
    int k0 = blockIdx.x * 32;
    if (k0 >= Lk) return;
    int d0 = blockIdx.y * 32;
    const __nv_bfloat16* X = (pl ? VHlp : VHhp) + (ll)s * PSTR;
    __nv_bfloat16*       Y = (pl ? VTlp : VThp) + (ll)s * PSTR;
    int tx = threadIdx.x, ty = threadIdx.y;
#pragma unroll
    for (int j = 0; j < 32; j += 8)
        t[ty + j][tx] = X[((ll)b * Lk + k0 + ty + j) * DS + d0 + tx];
    __syncthreads();
    int head = d0 >> 7;
    int dh0  = d0 & 127;
#pragma unroll
    for (int j = 0; j < 32; j += 8) {
        int d = dh0 + ty + j;
        Y[(ll)b * DS * Lk + (ll)head * HD * Lk + (ll)d * Lk + k0 + tx] = t[tx][ty + j];
    }
}

// ---------------- merged softmax across scales ----------------
__global__ void softmax_batch(float* __restrict__ S,
                              __nv_bfloat16* __restrict__ PH, __nv_bfloat16* __restrict__ PL)
{
    int y  = blockIdx.y;               // scale*8 + bh
    int sc = y >> 3, bh = y & 7;
    int Lk = d_LK[sc];
    ll base = d_SOFF[sc] + ((ll)bh * SEQ + blockIdx.x) * Lk;
    float* p = S + base;
    __nv_bfloat16* ph = PH + base;
    __nv_bfloat16* pl = PL + base;
    __shared__ float red[256];
    int tid = threadIdx.x;

    float m = -1e30f;
    for (int i = tid; i < Lk; i += 256) m = fmaxf(m, p[i]);
    red[tid] = m; __syncthreads();
    for (int s = 128; s > 0; s >>= 1) {
        if (tid < s) red[tid] = fmaxf(red[tid], red[tid + s]);
        __syncthreads();
    }
    m = red[0]; __syncthreads();

    float sum = 0.f;
    for (int i = tid; i < Lk; i += 256) {
        float e = __expf(p[i] - m);
        p[i] = e; sum += e;
    }
    red[tid] = sum; __syncthreads();
    for (int s = 128; s > 0; s >>= 1) {
        if (tid < s) red[tid] += red[tid + s];
        __syncthreads();
    }
    float inv = 1.f / red[0];
    for (int i = tid; i < Lk; i += 256) {
        float v = p[i] * inv;
        __nv_bfloat16 h = __float2bfloat16(v);
        ph[i] = h;
        pl[i] = __float2bfloat16(v - __bfloat162float(h));
    }
}

// ---------------- weights0 = mean of 2 heads (scale 0) ----------------
__global__ void meanw_kernel(const __nv_bfloat16* __restrict__ PH,
                             const __nv_bfloat16* __restrict__ PL, float* __restrict__ W)
{
    ll idx = (ll)blockIdx.x * blockDim.x + threadIdx.x;
    const ll per = (ll)SEQ * SEQ;
    const ll total = (ll)BATCH * per;
    if (idx >= total) return;
    ll b = idx / per, rest = idx - b * per;
    ll i0 = (b * 2 + 0) * per + rest;
    ll i1 = (b * 2 + 1) * per + rest;
    float v0 = __bfloat162float(PH[i0]) + __bfloat162float(PL[i0]);
    float v1 = __bfloat162float(PH[i1]) + __bfloat162float(PL[i1]);
    W[idx] = 0.5f * (v0 + v1);
}

// ---------------- host orchestration ----------------
extern "C" void kernel_launch(void* const* d_in, const int* in_sizes, int n_in,
                              void* d_out, int out_size)
{
    const float* query = (const float*)d_in[0];
    const float* key_  = (const float*)d_in[1];
    const float* value = (const float*)d_in[2];
    const float* wq    = (const float*)d_in[3];
    const float* bq    = (const float*)d_in[4];
    const float* wk    = (const float*)d_in[5];
    const float* bk    = (const float*)d_in[6];
    const float* wv    = (const float*)d_in[7];
    const float* bv    = (const float*)d_in[8];
    const float* in_w  = (const float*)d_in[9];
    const float* in_b  = (const float*)d_in[10];
    const float* out_w = (const float*)d_in[11];
    const float* out_b = (const float*)d_in[12];
    const float* fus_w = (const float*)d_in[13];
    const float* fus_b = (const float*)d_in[14];
    float* out = (float*)d_out;

    float* Sb;
    __nv_bfloat16 *Xqh,*Xql,*Xkh,*Xkl,*Xvh,*Xvl, *Qh,*Ql,*Kh,*Kl,*Vh,*Vl;
    __nv_bfloat16 *QHh,*QHl,*KHh,*KHl,*VHh,*VHl,*VTh,*VTl,*OHh,*OHl;
    __nv_bfloat16 *KPh,*KPl,*VPh,*VPl,*Ph,*Pl,*ATTh,*ATTl;
    __nv_bfloat16 *wqh,*wql,*wkh,*wkl,*wvh,*wvl,*iwh,*iwl,*owh,*owl,*fwh,*fwl;
    cudaGetSymbolAddress((void**)&Sb, g_S);
    cudaGetSymbolAddress((void**)&Ph,  g_Ph);  cudaGetSymbolAddress((void**)&Pl,  g_Pl);
    cudaGetSymbolAddress((void**)&Xqh, g_Xqh); cudaGetSymbolAddress((void**)&Xql, g_Xql);
    cudaGetSymbolAddress((void**)&Xkh, g_Xkh); cudaGetSymbolAddress((void**)&Xkl, g_Xkl);
    cudaGetSymbolAddress((void**)&Xvh, g_Xvh); cudaGetSymbolAddress((void**)&Xvl, g_Xvl);
    cudaGetSymbolAddress((void**)&Qh,  g_Qh);  cudaGetSymbolAddress((void**)&Ql,  g_Ql);
    cudaGetSymbolAddress((void**)&Kh,  g_Kh);  cudaGetSymbolAddress((void**)&Kl,  g_Kl);
    cudaGetSymbolAddress((void**)&Vh,  g_Vh);  cudaGetSymbolAddress((void**)&Vl,  g_Vl);
    cudaGetSymbolAddress((void**)&QHh, g_QHh); cudaGetSymbolAddress((void**)&QHl, g_QHl);
    cudaGetSymbolAddress((void**)&KHh, g_KHh); cudaGetSymbolAddress((void**)&KHl, g_KHl);
    cudaGetSymbolAddress((void**)&VHh, g_VHh); cudaGetSymbolAddress((void**)&VHl, g_VHl);
    cudaGetSymbolAddress((void**)&VTh, g_VTh); cudaGetSymbolAddress((void**)&VTl, g_VTl);
    cudaGetSymbolAddress((void**)&OHh, g_OHh); cudaGetSymbolAddress((void**)&OHl, g_OHl);
    cudaGetSymbolAddress((void**)&KPh, g_KPh); cudaGetSymbolAddress((void**)&KPl, g_KPl);
    cudaGetSymbolAddress((void**)&VPh, g_VPh); cudaGetSymbolAddress((void**)&VPl, g_VPl);
    cudaGetSymbolAddress((void**)&ATTh,g_ATTh);cudaGetSymbolAddress((void**)&ATTl,g_ATTl);
    cudaGetSymbolAddress((void**)&wqh, g_wqh); cudaGetSymbolAddress((void**)&wql, g_wql);
    cudaGetSymbolAddress((void**)&wkh, g_wkh); cudaGetSymbolAddress((void**)&wkl, g_wkl);
    cudaGetSymbolAddress((void**)&wvh, g_wvh); cudaGetSymbolAddress((void**)&wvl, g_wvl);
    cudaGetSymbolAddress((void**)&iwh, g_iwh); cudaGetSymbolAddress((void**)&iwl, g_iwl);
    cudaGetSymbolAddress((void**)&owh, g_owh); cudaGetSymbolAddress((void**)&owl, g_owl);
    cudaGetSymbolAddress((void**)&fwh, g_fwh); cudaGetSymbolAddress((void**)&fwl, g_fwl);

    cudaFuncSetAttribute(gemm_pre, cudaFuncAttributeMaxDynamicSharedMemorySize, GEMM_SMEM);

    const float alpha_s = 0.08838834764831845f;   // 1/sqrt(128)
    const int   LKs[4] = {2048, 1024, 512, 256};
    const int   MKs[4] = {8192, 4096, 2048, 1024};
    const ll    SOFFs[4] = {SOFF0, SOFF1, SOFF2, SOFF3};
    const ll    KPOFF[4] = {0, 0, 1048576, 1572864};   // index by scale (1..3 used)

    // ---- 0. all splits in one launch
    {
        STab t{};
        t.j[0] = {query, Xqh, Xql, (ll)MROWS * HID};
        t.j[1] = {key_,  Xkh, Xkl, (ll)MROWS * HID};
        t.j[2] = {value, Xvh, Xvl, (ll)MROWS * HID};
        t.j[3] = {wq, wqh, wql, (ll)HID * HID};
        t.j[4] = {wk, wkh, wkl, (ll)HID * HID};
        t.j[5] = {wv, wvh, wvl, (ll)HID * HID};
        t.j[6] = {in_w,  iwh, iwl, (ll)4 * 3 * DS * DS};
        t.j[7] = {out_w, owh, owl, (ll)4 * DS * DS};
        t.j[8] = {fus_w, fwh, fwl, (ll)HID * HID};
        split_batch<<<dim3(8192, 9), 256>>>(t);
    }

    // ---- 1. input projections (z = 3)
    {
        GTab t{};
        t.a[0] = {Xqh, Xql, wqh, wql, bq, nullptr, Qh, Ql, MROWS, HID, HID, HID, HID, HID, 1.f, 0};
        t.a[1] = {Xkh, Xkl, wkh, wkl, bk, nullptr, Kh, Kl, MROWS, HID, HID, HID, HID, HID, 1.f, 0};
        t.a[2] = {Xvh, Xvl, wvh, wvl, bv, nullptr, Vh, Vl, MROWS, HID, HID, HID, HID, HID, 1.f, 0};
        gemm_pre<<<dim3(8, 64, 3), 256, GEMM_SMEM>>>(t);
    }

    // ---- 2. pools (6 jobs: k/v x scales 2,4,8)
    {
        PTab t{};
        int jj = 0;
        for (int i = 1; i < 4; i++) {
            int s = 1 << i;
            t.j[jj++] = {Kh, Kl, KPh + KPOFF[i], KPl + KPOFF[i], MKs[i], s, i * DS, 0};
            t.j[jj++] = {Vh, Vl, VPh + KPOFF[i], VPl + KPOFF[i], MKs[i], s, i * DS, 0};
        }
        pool_batch<<<dim3(4096, 6), 256>>>(t);
    }

    // ---- 3. head projections (z = 12: q x4, k x4, v x4)
    {
        GTab t{};
        for (int i = 0; i < 4; i++) {
            ll wOff = (ll)i * 3 * DS * DS;
            const float* bi = in_b + (ll)i * 3 * DS;
            // q
            t.a[i] = {Qh + i * DS, Ql + i * DS, iwh + wOff, iwl + wOff, bi, nullptr,
                      QHh + (ll)i * PSTR, QHl + (ll)i * PSTR,
                      MROWS, DS, DS, HID, DS, DS, 1.f, 0};
            // k
            const __nv_bfloat16 *kah, *kal; int klda;
            if (i == 0) { kah = Kh + i * DS; kal = Kl + i * DS; klda = HID; }
            else        { kah = KPh + KPOFF[i]; kal = KPl + KPOFF[i]; klda = DS; }
            t.a[4 + i] = {kah, kal, iwh + wOff + DS * DS, iwl + wOff + DS * DS, bi + DS, nullptr,
                          KHh + (ll)i * PSTR, KHl + (ll)i * PSTR,
                          MKs[i], DS, DS, klda, DS, DS, 1.f, 0};
            // v
            const __nv_bfloat16 *vah, *val; int vlda;
            if (i == 0) { vah = Vh + i * DS; val = Vl + i * DS; vlda = HID; }
            else        { vah = VPh + KPOFF[i]; val = VPl + KPOFF[i]; vlda = DS; }
            t.a[8 + i] = {vah, val, iwh + wOff + 2 * DS * DS, iwl + wOff + 2 * DS * DS, bi + 2 * DS, nullptr,
                          VHh + (ll)i * PSTR, VHl + (ll)i * PSTR,
                          MKs[i], DS, DS, vlda, DS, DS, 1.f, 0};
        }
        gemm_pre<<<dim3(2, 64, 12), 256, GEMM_SMEM>>>(t);
    }

    // ---- 4. transposes (z = 32: plane x scale x batch)
    transpose_batch<<<dim3(64, 8, 32), dim3(32, 8)>>>(VHh, VHl, VTh, VTl);

    // ---- 5. scores (z = 32: scale x batch x head)
    {
        GTab t{};
        for (int i = 0; i < 4; i++)
            for (int b = 0; b < BATCH; b++)
                for (int h = 0; h < NH; h++) {
                    int z = i * 8 + b * 2 + h;
                    int Lk = LKs[i];
                    t.a[z] = {QHh + (ll)i * PSTR + (ll)b * SEQ * DS + h * HD,
                              QHl + (ll)i * PSTR + (ll)b * SEQ * DS + h * HD,
                              KHh + (ll)i * PSTR + (ll)b * Lk * DS + h * HD,
                              KHl + (ll)i * PSTR + (ll)b * Lk * DS + h * HD,
                              nullptr,
                              Sb + SOFFs[i] + (ll)(b * 2 + h) * SEQ * Lk,
                              nullptr, nullptr,
                              SEQ, Lk, HD, DS, DS, Lk, alpha_s, 0};
                }
        gemm_pre<<<dim3(16, 16, 32), 256, GEMM_SMEM>>>(t);
    }

    // ---- 6. softmax (all scales) + weights0
    softmax_batch<<<dim3(SEQ, 32), 256>>>(Sb, Ph, Pl);
    if ((ll)out_size >= (ll)MROWS * HID + (ll)BATCH * SEQ * SEQ) {
        ll tot = (ll)BATCH * SEQ * SEQ;
        meanw_kernel<<<(unsigned)((tot + 255) / 256), 256>>>(Ph, Pl, out + (ll)MROWS * HID);
    }

    // ---- 7. PV (z = 32)
    {
        GTab t{};
        for (int i = 0; i < 4; i++)
            for (int b = 0; b < BATCH; b++)
                for (int h = 0; h < NH; h++) {
                    int z = i * 8 + b * 2 + h;
                    int Lk = LKs[i];
                    t.a[z] = {Ph + SOFFs[i] + (ll)(b * 2 + h) * SEQ * Lk,
                              Pl + SOFFs[i] + (ll)(b * 2 + h) * SEQ * Lk,
                              VTh + (ll)i * PSTR + (ll)b * DS * Lk + (ll)h * HD * Lk,
                              VTl + (ll)i * PSTR + (ll)b * DS * Lk + (ll)h * HD * Lk,
                              nullptr, nullptr,
                              OHh + (ll)i * PSTR + (ll)b * SEQ * DS + h * HD,
                              OHl + (ll)i * PSTR + (ll)b * SEQ * DS + h * HD,
                              SEQ, HD, Lk, Lk, Lk, DS, 1.f, 0};
                }
        gemm_pre<<<dim3(1, 16, 32), 256, GEMM_SMEM>>>(t);
    }

    // ---- 8. out projections (z = 4)
    {
        GTab t{};
        for (int i = 0; i < 4; i++)
            t.a[i] = {OHh + (ll)i * PSTR, OHl + (ll)i * PSTR,
                      owh + (ll)i * DS * DS, owl + (ll)i * DS * DS,
                      out_b + i * DS, nullptr, ATTh + i * DS, ATTl + i * DS,
                      MROWS, DS, DS, DS, DS, HID, 1.f, 0};
        gemm_pre<<<dim3(2, 64, 4), 256, GEMM_SMEM>>>(t);
    }

    // ---- 9. fusion
    {
        GTab t{};
        t.a[0] = {ATTh, ATTl, fwh, fwl, fus_b, out, nullptr, nullptr,
                  MROWS, HID, HID, HID, HID, HID, 1.f, 0};
        gemm_pre<<<dim3(8, 64, 1), 256, GEMM_SMEM>>>(t);
    }
}